// round 1
// baseline (speedup 1.0000x reference)
#include <cuda_runtime.h>
#include <cuda_bf16.h>

#define NN 100000
#define NE 1600000
#define NG 64
#define DD 128
#define DO 4
#define LEAKY 0.01f

// ---------------- device scratch (static, allowed) ----------------
__device__ float  g_h[NN * DD];        // h = X @ W1           (51.2 MB)
__device__ float4 g_hh[NN];            // per-node layer-2 features (1.6 MB)
__device__ int    g_cnt[NN];           // in-degree (excl. self loop)
__device__ float  g_dis[NN];           // deg^{-1/2}
__device__ int    g_off[NN + 1];       // CSR offsets by dst
__device__ int    g_cur[NN];           // scatter cursors
__device__ int    g_csr[NE];           // CSR src indices
__device__ float  g_pool[NG * DO];     // per-graph sums

// ---------------- kernels ----------------
__global__ void k_init(int n) {
    int i = blockIdx.x * blockDim.x + threadIdx.x;
    if (i < n) g_cnt[i] = 0;
    if (i < NG * DO) g_pool[i] = 0.f;
}

__global__ void k_hist(const int* __restrict__ dst, int E) {
    int i = blockIdx.x * blockDim.x + threadIdx.x;
    if (i < E) atomicAdd(&g_cnt[dst[i]], 1);
}

__global__ void k_dis(int n) {
    int i = blockIdx.x * blockDim.x + threadIdx.x;
    if (i < n) g_dis[i] = rsqrtf((float)(g_cnt[i] + 1));  // +1 self loop
}

// single-block exclusive scan of g_cnt -> g_off, g_cur
__global__ void k_scan(int n) {
    __shared__ int ws[32];
    int tid = threadIdx.x, lane = tid & 31, wid = tid >> 5;
    int carry = 0;
    for (int base = 0; base < n; base += 1024) {
        int i = base + tid;
        int v = (i < n) ? g_cnt[i] : 0;
        int x = v;
#pragma unroll
        for (int d = 1; d < 32; d <<= 1) {
            int y = __shfl_up_sync(0xffffffffu, x, d);
            if (lane >= d) x += y;
        }
        if (lane == 31) ws[wid] = x;
        __syncthreads();
        if (wid == 0) {
            int s = ws[lane];
#pragma unroll
            for (int d = 1; d < 32; d <<= 1) {
                int y = __shfl_up_sync(0xffffffffu, s, d);
                if (lane >= d) s += y;
            }
            ws[lane] = s;  // inclusive scan of warp totals
        }
        __syncthreads();
        int warp_excl = (wid == 0) ? 0 : ws[wid - 1];
        int excl = carry + warp_excl + (x - v);
        if (i < n) { g_off[i] = excl; g_cur[i] = excl; }
        carry += ws[31];
        __syncthreads();
    }
    if (tid == 0) g_off[n] = carry;
}

__global__ void k_scatter(const int* __restrict__ src, const int* __restrict__ dst, int E) {
    int i = blockIdx.x * blockDim.x + threadIdx.x;
    if (i < E) {
        int d = dst[i];
        int p = atomicAdd(&g_cur[d], 1);
        g_csr[p] = src[i];
    }
}

// h = X @ W1 : block computes 64 rows x 128 cols; fp32 SIMT, smem tiled
__global__ void __launch_bounds__(256) k_gemm(const float* __restrict__ x,
                                              const float* __restrict__ W1, int n) {
    __shared__ float Xs[64][33];
    __shared__ float Ws[32][128];
    int tx = threadIdx.x;
    int row0 = blockIdx.x * 64;
    int cg = tx & 15;   // col group -> cols cg*8 .. cg*8+7
    int rg = tx >> 4;   // row group -> rows rg*4 .. rg*4+3
    float acc[4][8];
#pragma unroll
    for (int r = 0; r < 4; r++)
#pragma unroll
        for (int c = 0; c < 8; c++) acc[r][c] = 0.f;

    for (int kc = 0; kc < 4; kc++) {
        // load X tile 64x32
#pragma unroll
        for (int it = 0; it < 2; it++) {
            int idx = tx + 256 * it;        // float4 idx 0..511
            int r = idx >> 3, c4 = idx & 7;
            int grow = row0 + r;
            float4 v = make_float4(0.f, 0.f, 0.f, 0.f);
            if (grow < n) v = *(const float4*)&x[grow * DD + kc * 32 + c4 * 4];
            Xs[r][c4 * 4 + 0] = v.x; Xs[r][c4 * 4 + 1] = v.y;
            Xs[r][c4 * 4 + 2] = v.z; Xs[r][c4 * 4 + 3] = v.w;
        }
        // load W tile 32x128
#pragma unroll
        for (int it = 0; it < 4; it++) {
            int idx = tx + 256 * it;        // float4 idx 0..1023
            int r = idx >> 5, c4 = idx & 31;
            *(float4*)&Ws[r][c4 * 4] = *(const float4*)&W1[(kc * 32 + r) * DD + c4 * 4];
        }
        __syncthreads();
#pragma unroll
        for (int k = 0; k < 32; k++) {
            float a0 = Xs[rg * 4 + 0][k];
            float a1 = Xs[rg * 4 + 1][k];
            float a2 = Xs[rg * 4 + 2][k];
            float a3 = Xs[rg * 4 + 3][k];
            float4 bA = *(float4*)&Ws[k][cg * 8];
            float4 bB = *(float4*)&Ws[k][cg * 8 + 4];
            float bcol[8] = {bA.x, bA.y, bA.z, bA.w, bB.x, bB.y, bB.z, bB.w};
#pragma unroll
            for (int c = 0; c < 8; c++) {
                acc[0][c] += a0 * bcol[c];
                acc[1][c] += a1 * bcol[c];
                acc[2][c] += a2 * bcol[c];
                acc[3][c] += a3 * bcol[c];
            }
        }
        __syncthreads();
    }
#pragma unroll
    for (int r = 0; r < 4; r++) {
        int grow = row0 + rg * 4 + r;
        if (grow < n) {
            *(float4*)&g_h[grow * DD + cg * 8] =
                make_float4(acc[r][0], acc[r][1], acc[r][2], acc[r][3]);
            *(float4*)&g_h[grow * DD + cg * 8 + 4] =
                make_float4(acc[r][4], acc[r][5], acc[r][6], acc[r][7]);
        }
    }
}

// gather-propagate + bias + LeakyReLU + @W2 fused; one warp per dst node
__global__ void __launch_bounds__(256) k_prop(const float* __restrict__ b1,
                                              const float* __restrict__ W2, int n) {
    __shared__ float4 W2s[128];  // W2 row d -> 4 outputs
    int tid = threadIdx.x;
    if (tid < 128) W2s[tid] = *(const float4*)&W2[tid * 4];
    __syncthreads();
    int wid = tid >> 5, lane = tid & 31;
    int node = blockIdx.x * 8 + wid;
    if (node >= n) return;

    const float4* h4 = (const float4*)g_h;
    float dn = g_dis[node];
    float wself = dn * dn;
    float4 v = h4[node * 32 + lane];
    float ax = v.x * wself, ay = v.y * wself, az = v.z * wself, aw = v.w * wself;

    int beg = g_off[node], end = g_off[node + 1];
    for (int i = beg; i < end; i++) {
        int s = g_csr[i];
        float w = g_dis[s] * dn;
        float4 u = h4[s * 32 + lane];
        ax += u.x * w; ay += u.y * w; az += u.z * w; aw += u.w * w;
    }
    float4 bb = *(const float4*)&b1[lane * 4];
    ax += bb.x; ay += bb.y; az += bb.z; aw += bb.w;
    ax = (ax >= 0.f) ? ax : LEAKY * ax;
    ay = (ay >= 0.f) ? ay : LEAKY * ay;
    az = (az >= 0.f) ? az : LEAKY * az;
    aw = (aw >= 0.f) ? aw : LEAKY * aw;

    float act[4] = {ax, ay, az, aw};
    float o0 = 0.f, o1 = 0.f, o2 = 0.f, o3 = 0.f;
#pragma unroll
    for (int j = 0; j < 4; j++) {
        float4 wr = W2s[lane * 4 + j];
        o0 += act[j] * wr.x; o1 += act[j] * wr.y;
        o2 += act[j] * wr.z; o3 += act[j] * wr.w;
    }
#pragma unroll
    for (int off = 16; off; off >>= 1) {
        o0 += __shfl_down_sync(0xffffffffu, o0, off);
        o1 += __shfl_down_sync(0xffffffffu, o1, off);
        o2 += __shfl_down_sync(0xffffffffu, o2, off);
        o3 += __shfl_down_sync(0xffffffffu, o3, off);
    }
    if (lane == 0) g_hh[node] = make_float4(o0, o1, o2, o3);
}

// stream all edges (+ self loops), accumulate directly into per-graph buckets
__global__ void __launch_bounds__(256) k_pool(const int* __restrict__ src,
                                              const int* __restrict__ dst,
                                              const int* __restrict__ batch,
                                              int n, int E) {
    __shared__ float sb[NG * DO];
    if (threadIdx.x < NG * DO) sb[threadIdx.x] = 0.f;
    __syncthreads();
    int total = E + n;
    for (int i = blockIdx.x * blockDim.x + threadIdx.x; i < total;
         i += gridDim.x * blockDim.x) {
        int s, g; float w;
        if (i < E) {
            s = src[i];
            int d = dst[i];
            w = g_dis[s] * g_dis[d];
            g = batch[d];
        } else {
            int m = i - E;
            s = m;
            float dm = g_dis[m];
            w = dm * dm;
            g = batch[m];
        }
        float4 v = g_hh[s];
        atomicAdd(&sb[g * 4 + 0], v.x * w);
        atomicAdd(&sb[g * 4 + 1], v.y * w);
        atomicAdd(&sb[g * 4 + 2], v.z * w);
        atomicAdd(&sb[g * 4 + 3], v.w * w);
    }
    __syncthreads();
    if (threadIdx.x < NG * DO) atomicAdd(&g_pool[threadIdx.x], sb[threadIdx.x]);
}

// per-graph mean (+b2) and softmax; counts via binary search in sorted batch
__global__ void k_final(const int* __restrict__ batch, const float* __restrict__ b2,
                        float* __restrict__ out, int n) {
    int g = threadIdx.x;
    if (g >= NG) return;
    int lo = 0, hi = n;
    while (lo < hi) { int m = (lo + hi) >> 1; if (batch[m] < g) lo = m + 1; else hi = m; }
    int a = lo;
    lo = 0; hi = n;
    while (lo < hi) { int m = (lo + hi) >> 1; if (batch[m] < g + 1) lo = m + 1; else hi = m; }
    int c = lo - a;
    float v[4];
    if (c > 0) {
        float inv = 1.f / (float)c;
#pragma unroll
        for (int o = 0; o < 4; o++) v[o] = g_pool[g * 4 + o] * inv + b2[o];
    } else {
#pragma unroll
        for (int o = 0; o < 4; o++) v[o] = 0.f;
    }
    float mx = fmaxf(fmaxf(v[0], v[1]), fmaxf(v[2], v[3]));
    float e[4], s = 0.f;
#pragma unroll
    for (int o = 0; o < 4; o++) { e[o] = __expf(v[o] - mx); s += e[o]; }
    float inv = 1.f / s;
#pragma unroll
    for (int o = 0; o < 4; o++) out[g * 4 + o] = e[o] * inv;
}

// ---------------- launch ----------------
extern "C" void kernel_launch(void* const* d_in, const int* in_sizes, int n_in,
                              void* d_out, int out_size) {
    const float* x     = (const float*)d_in[0];
    const int*   ei    = (const int*)d_in[1];
    const int*   batch = (const int*)d_in[2];
    const float* W1    = (const float*)d_in[3];
    const float* b1    = (const float*)d_in[4];
    const float* W2    = (const float*)d_in[5];
    const float* b2    = (const float*)d_in[6];

    int n = in_sizes[0] / DD;
    int E = in_sizes[1] / 2;
    const int* src = ei;
    const int* dst = ei + E;

    k_init<<<(n + 255) / 256, 256>>>(n);
    k_hist<<<(E + 255) / 256, 256>>>(dst, E);
    k_dis<<<(n + 255) / 256, 256>>>(n);
    k_scan<<<1, 1024>>>(n);
    k_scatter<<<(E + 255) / 256, 256>>>(src, dst, E);
    k_gemm<<<(n + 63) / 64, 256>>>(x, W1, n);
    k_prop<<<(n + 7) / 8, 256>>>(b1, W2, n);
    k_pool<<<1184, 256>>>(src, dst, batch, n, E);
    k_final<<<1, 64>>>(batch, b2, (float*)d_out, n);
}

// round 2
// speedup vs baseline: 1.1837x; 1.1837x over previous
#include <cuda_runtime.h>
#include <cuda_bf16.h>

#define NN 100000
#define NE 1600000
#define NG 64
#define DD 128
#define DO 4
#define LEAKY 0.01f
#define SCAN_B 1024
#define NBLK ((NN + SCAN_B - 1) / SCAN_B)   // 98

// ---------------- device scratch (static, allowed) ----------------
__device__ float  g_h[NN * DD];        // h = X @ W1           (51.2 MB)
__device__ float4 g_hh[NN];            // per-node layer-2 features (1.6 MB)
__device__ int    g_cnt[NN];           // in-degree (excl. self loop)
__device__ float  g_dis[NN];           // deg^{-1/2}
__device__ int    g_off[NN + 1];       // CSR offsets by dst
__device__ int    g_cur[NN];           // scatter cursors
__device__ int    g_csr[NE];           // CSR src indices
__device__ float  g_pool[NG * DO];     // per-graph sums
__device__ int    g_bsum[NBLK];        // scan block totals
__device__ int    g_bpre[NBLK];        // scan block exclusive prefixes

// ---------------- kernels ----------------
__global__ void k_init(int n) {
    int i = blockIdx.x * blockDim.x + threadIdx.x;
    if (i < n) g_cnt[i] = 0;
    if (i < NG * DO) g_pool[i] = 0.f;
}

__global__ void k_hist(const int* __restrict__ dst, int E) {
    int i = blockIdx.x * blockDim.x + threadIdx.x;
    if (i < E) atomicAdd(&g_cnt[dst[i]], 1);
}

// scan pass 1: per-block local exclusive scan of g_cnt -> g_off, block total -> g_bsum
__global__ void __launch_bounds__(SCAN_B) k_scan1(int n) {
    __shared__ int ws[32];
    int tid = threadIdx.x, lane = tid & 31, wid = tid >> 5;
    int i = blockIdx.x * SCAN_B + tid;
    int v = (i < n) ? g_cnt[i] : 0;
    int x = v;
#pragma unroll
    for (int d = 1; d < 32; d <<= 1) {
        int y = __shfl_up_sync(0xffffffffu, x, d);
        if (lane >= d) x += y;
    }
    if (lane == 31) ws[wid] = x;
    __syncthreads();
    if (wid == 0) {
        int s = ws[lane];
#pragma unroll
        for (int d = 1; d < 32; d <<= 1) {
            int y = __shfl_up_sync(0xffffffffu, s, d);
            if (lane >= d) s += y;
        }
        ws[lane] = s;  // inclusive scan of warp totals
    }
    __syncthreads();
    int warp_excl = (wid == 0) ? 0 : ws[wid - 1];
    if (i < n) g_off[i] = warp_excl + (x - v);     // block-local exclusive
    if (tid == SCAN_B - 1) g_bsum[blockIdx.x] = warp_excl + x;
}

// scan pass 2: one block scans the NBLK block totals
__global__ void k_scan2(int nb, int n) {
    __shared__ int ws[4];
    int tid = threadIdx.x, lane = tid & 31, wid = tid >> 5;  // 128 threads
    int v = (tid < nb) ? g_bsum[tid] : 0;
    int x = v;
#pragma unroll
    for (int d = 1; d < 32; d <<= 1) {
        int y = __shfl_up_sync(0xffffffffu, x, d);
        if (lane >= d) x += y;
    }
    if (lane == 31) ws[wid] = x;
    __syncthreads();
    if (tid == 0) {
        int c = 0;
#pragma unroll
        for (int w = 0; w < 4; w++) { int t = ws[w]; ws[w] = c; c += t; }
        g_off[n] = c;   // grand total
    }
    __syncthreads();
    if (tid < nb) g_bpre[tid] = ws[wid] + (x - v);
}

// scan pass 3: fixup offsets, init cursors, compute deg^{-1/2}
__global__ void __launch_bounds__(SCAN_B) k_scan3(int n) {
    int i = blockIdx.x * SCAN_B + threadIdx.x;
    if (i < n) {
        int o = g_off[i] + g_bpre[blockIdx.x];
        g_off[i] = o;
        g_cur[i] = o;
        g_dis[i] = rsqrtf((float)(g_cnt[i] + 1));  // +1 self loop
    }
}

__global__ void k_scatter(const int* __restrict__ src, const int* __restrict__ dst, int E) {
    int i = blockIdx.x * blockDim.x + threadIdx.x;
    if (i < E) {
        int d = dst[i];
        int p = atomicAdd(&g_cur[d], 1);
        g_csr[p] = src[i];
    }
}

// h = X @ W1 : block computes 64 rows x 128 cols; fp32 SIMT, smem tiled
__global__ void __launch_bounds__(256) k_gemm(const float* __restrict__ x,
                                              const float* __restrict__ W1, int n) {
    __shared__ float Xs[64][33];
    __shared__ float Ws[32][128];
    int tx = threadIdx.x;
    int row0 = blockIdx.x * 64;
    int cg = tx & 15;   // col group -> cols cg*8 .. cg*8+7
    int rg = tx >> 4;   // row group -> rows rg*4 .. rg*4+3
    float acc[4][8];
#pragma unroll
    for (int r = 0; r < 4; r++)
#pragma unroll
        for (int c = 0; c < 8; c++) acc[r][c] = 0.f;

    for (int kc = 0; kc < 4; kc++) {
        // load X tile 64x32
#pragma unroll
        for (int it = 0; it < 2; it++) {
            int idx = tx + 256 * it;        // float4 idx 0..511
            int r = idx >> 3, c4 = idx & 7;
            int grow = row0 + r;
            float4 v = make_float4(0.f, 0.f, 0.f, 0.f);
            if (grow < n) v = *(const float4*)&x[grow * DD + kc * 32 + c4 * 4];
            Xs[r][c4 * 4 + 0] = v.x; Xs[r][c4 * 4 + 1] = v.y;
            Xs[r][c4 * 4 + 2] = v.z; Xs[r][c4 * 4 + 3] = v.w;
        }
        // load W tile 32x128
#pragma unroll
        for (int it = 0; it < 4; it++) {
            int idx = tx + 256 * it;        // float4 idx 0..1023
            int r = idx >> 5, c4 = idx & 31;
            *(float4*)&Ws[r][c4 * 4] = *(const float4*)&W1[(kc * 32 + r) * DD + c4 * 4];
        }
        __syncthreads();
#pragma unroll
        for (int k = 0; k < 32; k++) {
            float a0 = Xs[rg * 4 + 0][k];
            float a1 = Xs[rg * 4 + 1][k];
            float a2 = Xs[rg * 4 + 2][k];
            float a3 = Xs[rg * 4 + 3][k];
            float4 bA = *(float4*)&Ws[k][cg * 8];
            float4 bB = *(float4*)&Ws[k][cg * 8 + 4];
            float bcol[8] = {bA.x, bA.y, bA.z, bA.w, bB.x, bB.y, bB.z, bB.w};
#pragma unroll
            for (int c = 0; c < 8; c++) {
                acc[0][c] += a0 * bcol[c];
                acc[1][c] += a1 * bcol[c];
                acc[2][c] += a2 * bcol[c];
                acc[3][c] += a3 * bcol[c];
            }
        }
        __syncthreads();
    }
#pragma unroll
    for (int r = 0; r < 4; r++) {
        int grow = row0 + rg * 4 + r;
        if (grow < n) {
            *(float4*)&g_h[grow * DD + cg * 8] =
                make_float4(acc[r][0], acc[r][1], acc[r][2], acc[r][3]);
            *(float4*)&g_h[grow * DD + cg * 8 + 4] =
                make_float4(acc[r][4], acc[r][5], acc[r][6], acc[r][7]);
        }
    }
}

// gather-propagate + bias + LeakyReLU + @W2 fused; one warp per dst node
__global__ void __launch_bounds__(256) k_prop(const float* __restrict__ b1,
                                              const float* __restrict__ W2, int n) {
    __shared__ float4 W2s[128];  // W2 row d -> 4 outputs
    int tid = threadIdx.x;
    if (tid < 128) W2s[tid] = *(const float4*)&W2[tid * 4];
    __syncthreads();
    int wid = tid >> 5, lane = tid & 31;
    int node = blockIdx.x * 8 + wid;
    if (node >= n) return;

    const float4* h4 = (const float4*)g_h;
    float dn = g_dis[node];
    float wself = dn * dn;
    float4 v = h4[node * 32 + lane];
    float ax = v.x * wself, ay = v.y * wself, az = v.z * wself, aw = v.w * wself;

    int beg = g_off[node], end = g_off[node + 1];
    for (int i = beg; i < end; i++) {
        int s = g_csr[i];
        float w = g_dis[s] * dn;
        float4 u = h4[s * 32 + lane];
        ax += u.x * w; ay += u.y * w; az += u.z * w; aw += u.w * w;
    }
    float4 bb = *(const float4*)&b1[lane * 4];
    ax += bb.x; ay += bb.y; az += bb.z; aw += bb.w;
    ax = (ax >= 0.f) ? ax : LEAKY * ax;
    ay = (ay >= 0.f) ? ay : LEAKY * ay;
    az = (az >= 0.f) ? az : LEAKY * az;
    aw = (aw >= 0.f) ? aw : LEAKY * aw;

    float act[4] = {ax, ay, az, aw};
    float o0 = 0.f, o1 = 0.f, o2 = 0.f, o3 = 0.f;
#pragma unroll
    for (int j = 0; j < 4; j++) {
        float4 wr = W2s[lane * 4 + j];
        o0 += act[j] * wr.x; o1 += act[j] * wr.y;
        o2 += act[j] * wr.z; o3 += act[j] * wr.w;
    }
#pragma unroll
    for (int off = 16; off; off >>= 1) {
        o0 += __shfl_down_sync(0xffffffffu, o0, off);
        o1 += __shfl_down_sync(0xffffffffu, o1, off);
        o2 += __shfl_down_sync(0xffffffffu, o2, off);
        o3 += __shfl_down_sync(0xffffffffu, o3, off);
    }
    if (lane == 0) g_hh[node] = make_float4(o0, o1, o2, o3);
}

// stream all edges (+ self loops), accumulate directly into per-graph buckets
__global__ void __launch_bounds__(256) k_pool(const int* __restrict__ src,
                                              const int* __restrict__ dst,
                                              const int* __restrict__ batch,
                                              int n, int E) {
    __shared__ float sb[NG * DO];
    if (threadIdx.x < NG * DO) sb[threadIdx.x] = 0.f;
    __syncthreads();
    int total = E + n;
    for (int i = blockIdx.x * blockDim.x + threadIdx.x; i < total;
         i += gridDim.x * blockDim.x) {
        int s, g; float w;
        if (i < E) {
            s = src[i];
            int d = dst[i];
            w = g_dis[s] * g_dis[d];
            g = batch[d];
        } else {
            int m = i - E;
            s = m;
            float dm = g_dis[m];
            w = dm * dm;
            g = batch[m];
        }
        float4 v = g_hh[s];
        atomicAdd(&sb[g * 4 + 0], v.x * w);
        atomicAdd(&sb[g * 4 + 1], v.y * w);
        atomicAdd(&sb[g * 4 + 2], v.z * w);
        atomicAdd(&sb[g * 4 + 3], v.w * w);
    }
    __syncthreads();
    if (threadIdx.x < NG * DO) atomicAdd(&g_pool[threadIdx.x], sb[threadIdx.x]);
}

// per-graph mean (+b2) and softmax; counts via binary search in sorted batch
__global__ void k_final(const int* __restrict__ batch, const float* __restrict__ b2,
                        float* __restrict__ out, int n) {
    int g = threadIdx.x;
    if (g >= NG) return;
    int lo = 0, hi = n;
    while (lo < hi) { int m = (lo + hi) >> 1; if (batch[m] < g) lo = m + 1; else hi = m; }
    int a = lo;
    lo = 0; hi = n;
    while (lo < hi) { int m = (lo + hi) >> 1; if (batch[m] < g + 1) lo = m + 1; else hi = m; }
    int c = lo - a;
    float v[4];
    if (c > 0) {
        float inv = 1.f / (float)c;
#pragma unroll
        for (int o = 0; o < 4; o++) v[o] = g_pool[g * 4 + o] * inv + b2[o];
    } else {
#pragma unroll
        for (int o = 0; o < 4; o++) v[o] = 0.f;
    }
    float mx = fmaxf(fmaxf(v[0], v[1]), fmaxf(v[2], v[3]));
    float e[4], s = 0.f;
#pragma unroll
    for (int o = 0; o < 4; o++) { e[o] = __expf(v[o] - mx); s += e[o]; }
    float inv = 1.f / s;
#pragma unroll
    for (int o = 0; o < 4; o++) out[g * 4 + o] = e[o] * inv;
}

// ---------------- launch ----------------
extern "C" void kernel_launch(void* const* d_in, const int* in_sizes, int n_in,
                              void* d_out, int out_size) {
    const float* x     = (const float*)d_in[0];
    const int*   ei    = (const int*)d_in[1];
    const int*   batch = (const int*)d_in[2];
    const float* W1    = (const float*)d_in[3];
    const float* b1    = (const float*)d_in[4];
    const float* W2    = (const float*)d_in[5];
    const float* b2    = (const float*)d_in[6];

    int n = in_sizes[0] / DD;
    int E = in_sizes[1] / 2;
    const int* src = ei;
    const int* dst = ei + E;
    int nb = (n + SCAN_B - 1) / SCAN_B;

    k_init<<<(n + 255) / 256, 256>>>(n);
    k_hist<<<(E + 255) / 256, 256>>>(dst, E);
    k_scan1<<<nb, SCAN_B>>>(n);
    k_scan2<<<1, 128>>>(nb, n);
    k_scan3<<<nb, SCAN_B>>>(n);
    k_scatter<<<(E + 255) / 256, 256>>>(src, dst, E);
    k_gemm<<<(n + 63) / 64, 256>>>(x, W1, n);
    k_prop<<<(n + 7) / 8, 256>>>(b1, W2, n);
    k_pool<<<1184, 256>>>(src, dst, batch, n, E);
    k_final<<<1, 64>>>(batch, b2, (float*)d_out, n);
}

// round 3
// speedup vs baseline: 1.6808x; 1.4199x over previous
#include <cuda_runtime.h>
#include <cuda_bf16.h>
#include <cstdint>

#define NN 100000
#define NE 1600000
#define NG 64
#define DD 128
#define DO 4
#define LEAKY 0.01f
#define SCAN_B 1024
#define NBLK ((NN + SCAN_B - 1) / SCAN_B)   // 98

// ---------------- device scratch (static, allowed) ----------------
__device__ __nv_bfloat16 g_hb[NN * DD];    // h = X @ W1 in bf16 (25.6 MB)
__device__ float4 g_hh[NN];            // per-node layer-2 features (1.6 MB)
__device__ int    g_cnt[NN];           // in-degree (excl. self loop)
__device__ float  g_dis[NN];           // deg^{-1/2}
__device__ int    g_off[NN + 1];       // CSR offsets by dst
__device__ int    g_cur[NN];           // scatter cursors
__device__ int    g_csr[NE];           // CSR src indices
__device__ float  g_pool[NG * DO];     // per-graph sums
__device__ int    g_bsum[NBLK];        // scan block totals
__device__ int    g_bpre[NBLK];        // scan block exclusive prefixes

__device__ __forceinline__ float tf32r(float v) {
    asm("cvt.rna.tf32.f32 %0, %1;" : "=f"(v) : "f"(v));
    return v;
}

// ---------------- kernels ----------------
__global__ void k_init(int n) {
    int i = blockIdx.x * blockDim.x + threadIdx.x;
    if (i < n) g_cnt[i] = 0;
    if (i < NG * DO) g_pool[i] = 0.f;
}

__global__ void k_hist(const int* __restrict__ dst, int E) {
    int i = blockIdx.x * blockDim.x + threadIdx.x;
    if (i < E) atomicAdd(&g_cnt[dst[i]], 1);
}

// scan pass 1: per-block local exclusive scan of g_cnt -> g_off, block total -> g_bsum
__global__ void __launch_bounds__(SCAN_B) k_scan1(int n) {
    __shared__ int ws[32];
    int tid = threadIdx.x, lane = tid & 31, wid = tid >> 5;
    int i = blockIdx.x * SCAN_B + tid;
    int v = (i < n) ? g_cnt[i] : 0;
    int x = v;
#pragma unroll
    for (int d = 1; d < 32; d <<= 1) {
        int y = __shfl_up_sync(0xffffffffu, x, d);
        if (lane >= d) x += y;
    }
    if (lane == 31) ws[wid] = x;
    __syncthreads();
    if (wid == 0) {
        int s = ws[lane];
#pragma unroll
        for (int d = 1; d < 32; d <<= 1) {
            int y = __shfl_up_sync(0xffffffffu, s, d);
            if (lane >= d) s += y;
        }
        ws[lane] = s;  // inclusive scan of warp totals
    }
    __syncthreads();
    int warp_excl = (wid == 0) ? 0 : ws[wid - 1];
    if (i < n) g_off[i] = warp_excl + (x - v);     // block-local exclusive
    if (tid == SCAN_B - 1) g_bsum[blockIdx.x] = warp_excl + x;
}

// scan pass 2: one block scans the NBLK block totals
__global__ void k_scan2(int nb, int n) {
    __shared__ int ws[4];
    int tid = threadIdx.x, lane = tid & 31, wid = tid >> 5;  // 128 threads
    int v = (tid < nb) ? g_bsum[tid] : 0;
    int x = v;
#pragma unroll
    for (int d = 1; d < 32; d <<= 1) {
        int y = __shfl_up_sync(0xffffffffu, x, d);
        if (lane >= d) x += y;
    }
    if (lane == 31) ws[wid] = x;
    __syncthreads();
    if (tid == 0) {
        int c = 0;
#pragma unroll
        for (int w = 0; w < 4; w++) { int t = ws[w]; ws[w] = c; c += t; }
        g_off[n] = c;   // grand total
    }
    __syncthreads();
    if (tid < nb) g_bpre[tid] = ws[wid] + (x - v);
}

// scan pass 3: fixup offsets, init cursors, compute deg^{-1/2}
__global__ void __launch_bounds__(SCAN_B) k_scan3(int n) {
    int i = blockIdx.x * SCAN_B + threadIdx.x;
    if (i < n) {
        int o = g_off[i] + g_bpre[blockIdx.x];
        g_off[i] = o;
        g_cur[i] = o;
        g_dis[i] = rsqrtf((float)(g_cnt[i] + 1));  // +1 self loop
    }
}

__global__ void k_scatter(const int* __restrict__ src, const int* __restrict__ dst, int E) {
    int i = blockIdx.x * blockDim.x + threadIdx.x;
    if (i < E) {
        int d = dst[i];
        int p = atomicAdd(&g_cur[d], 1);
        g_csr[p] = src[i];
    }
}

// h = X @ W1 via tf32 mma.sync, output bf16.
// Block tile: 128 M x 128 N. 8 warps, warp w owns rows m0+w*16 .. +16, all N.
// W1^T staged in smem, k-permuted so each B fragment is one 8B LDS.
__global__ void __launch_bounds__(256) k_gemm(const float* __restrict__ x,
                                              const float* __restrict__ W1, int n) {
    __shared__ float Wt[128 * 72];   // [n][k-half perm], row stride 72 floats
    int tid = threadIdx.x;
    int lane = tid & 31, warp = tid >> 5;
    int m0 = blockIdx.x * 128 + warp * 16;
    int gid = lane >> 2;   // 0..7
    int tig = lane & 3;    // 0..3

    float acc[16][4];
#pragma unroll
    for (int t = 0; t < 16; t++)
#pragma unroll
        for (int j = 0; j < 4; j++) acc[t][j] = 0.f;

    int ra = m0 + gid, rb = m0 + gid + 8;
    bool va = ra < n, vb = rb < n;
    const float* xa = x + (size_t)ra * DD;
    const float* xb = x + (size_t)rb * DD;

    for (int half = 0; half < 2; half++) {
        __syncthreads();
        // stage Wt[n][k] for k in [half*64, half*64+64), perm within k8 groups
        for (int idx = tid; idx < 64 * 128; idx += 256) {
            int kl = idx >> 7;          // local k 0..63
            int nn = idx & 127;
            float v = W1[(half * 64 + kl) * DD + nn];
            int kc = kl >> 3, k8 = kl & 7;
            int pos = kc * 8 + ((k8 & 3) << 1) + (k8 >> 2);
            Wt[nn * 72 + pos] = tf32r(v);
        }
        __syncthreads();
#pragma unroll
        for (int kc = 0; kc < 8; kc++) {
            int kb = half * 64 + kc * 8;
            float a0 = 0.f, a1 = 0.f, a2 = 0.f, a3 = 0.f;
            if (va) { a0 = xa[kb + tig]; a2 = xa[kb + tig + 4]; }
            if (vb) { a1 = xb[kb + tig]; a3 = xb[kb + tig + 4]; }
            a0 = tf32r(a0); a1 = tf32r(a1); a2 = tf32r(a2); a3 = tf32r(a3);
            uint32_t ua0 = __float_as_uint(a0), ua1 = __float_as_uint(a1);
            uint32_t ua2 = __float_as_uint(a2), ua3 = __float_as_uint(a3);
#pragma unroll
            for (int t = 0; t < 16; t++) {
                float2 b = *(const float2*)&Wt[(t * 8 + gid) * 72 + kc * 8 + 2 * tig];
                uint32_t ub0 = __float_as_uint(b.x), ub1 = __float_as_uint(b.y);
                asm volatile(
                    "mma.sync.aligned.m16n8k8.row.col.f32.tf32.tf32.f32 "
                    "{%0,%1,%2,%3},{%4,%5,%6,%7},{%8,%9},{%0,%1,%2,%3};"
                    : "+f"(acc[t][0]), "+f"(acc[t][1]), "+f"(acc[t][2]), "+f"(acc[t][3])
                    : "r"(ua0), "r"(ua1), "r"(ua2), "r"(ua3), "r"(ub0), "r"(ub1));
            }
        }
    }
    // store bf16
#pragma unroll
    for (int t = 0; t < 16; t++) {
        int c0 = t * 8 + 2 * tig;
        if (va) {
            __nv_bfloat162 p = __float22bfloat162_rn(make_float2(acc[t][0], acc[t][1]));
            *(__nv_bfloat162*)&g_hb[(size_t)ra * DD + c0] = p;
        }
        if (vb) {
            __nv_bfloat162 p = __float22bfloat162_rn(make_float2(acc[t][2], acc[t][3]));
            *(__nv_bfloat162*)&g_hb[(size_t)rb * DD + c0] = p;
        }
    }
}

// gather-propagate + bias + LeakyReLU + @W2 fused; one warp per dst node
__global__ void __launch_bounds__(256) k_prop(const float* __restrict__ b1,
                                              const float* __restrict__ W2, int n) {
    __shared__ float4 W2s[128];  // W2 row d -> 4 outputs
    int tid = threadIdx.x;
    if (tid < 128) W2s[tid] = *(const float4*)&W2[tid * 4];
    __syncthreads();
    int wid = tid >> 5, lane = tid & 31;
    int node = blockIdx.x * 8 + wid;
    if (node >= n) return;

    float dn = g_dis[node];
    float wself = dn * dn;
    float ax, ay, az, aw;
    {
        uint2 raw = *(const uint2*)&g_hb[(size_t)node * DD + lane * 4];
        float2 f0 = __bfloat1622float2(*reinterpret_cast<__nv_bfloat162*>(&raw.x));
        float2 f1 = __bfloat1622float2(*reinterpret_cast<__nv_bfloat162*>(&raw.y));
        ax = f0.x * wself; ay = f0.y * wself; az = f1.x * wself; aw = f1.y * wself;
    }

    int beg = g_off[node], end = g_off[node + 1];
    int i = beg;
    for (; i + 4 <= end; i += 4) {
        int s0 = g_csr[i], s1 = g_csr[i + 1], s2 = g_csr[i + 2], s3 = g_csr[i + 3];
        float w0 = g_dis[s0] * dn, w1 = g_dis[s1] * dn;
        float w2 = g_dis[s2] * dn, w3 = g_dis[s3] * dn;
        uint2 r0 = *(const uint2*)&g_hb[(size_t)s0 * DD + lane * 4];
        uint2 r1 = *(const uint2*)&g_hb[(size_t)s1 * DD + lane * 4];
        uint2 r2 = *(const uint2*)&g_hb[(size_t)s2 * DD + lane * 4];
        uint2 r3 = *(const uint2*)&g_hb[(size_t)s3 * DD + lane * 4];
        float2 f;
        f = __bfloat1622float2(*reinterpret_cast<__nv_bfloat162*>(&r0.x)); ax += f.x * w0; ay += f.y * w0;
        f = __bfloat1622float2(*reinterpret_cast<__nv_bfloat162*>(&r0.y)); az += f.x * w0; aw += f.y * w0;
        f = __bfloat1622float2(*reinterpret_cast<__nv_bfloat162*>(&r1.x)); ax += f.x * w1; ay += f.y * w1;
        f = __bfloat1622float2(*reinterpret_cast<__nv_bfloat162*>(&r1.y)); az += f.x * w1; aw += f.y * w1;
        f = __bfloat1622float2(*reinterpret_cast<__nv_bfloat162*>(&r2.x)); ax += f.x * w2; ay += f.y * w2;
        f = __bfloat1622float2(*reinterpret_cast<__nv_bfloat162*>(&r2.y)); az += f.x * w2; aw += f.y * w2;
        f = __bfloat1622float2(*reinterpret_cast<__nv_bfloat162*>(&r3.x)); ax += f.x * w3; ay += f.y * w3;
        f = __bfloat1622float2(*reinterpret_cast<__nv_bfloat162*>(&r3.y)); az += f.x * w3; aw += f.y * w3;
    }
    for (; i < end; i++) {
        int s = g_csr[i];
        float w = g_dis[s] * dn;
        uint2 r = *(const uint2*)&g_hb[(size_t)s * DD + lane * 4];
        float2 f;
        f = __bfloat1622float2(*reinterpret_cast<__nv_bfloat162*>(&r.x)); ax += f.x * w; ay += f.y * w;
        f = __bfloat1622float2(*reinterpret_cast<__nv_bfloat162*>(&r.y)); az += f.x * w; aw += f.y * w;
    }
    float4 bb = *(const float4*)&b1[lane * 4];
    ax += bb.x; ay += bb.y; az += bb.z; aw += bb.w;
    ax = (ax >= 0.f) ? ax : LEAKY * ax;
    ay = (ay >= 0.f) ? ay : LEAKY * ay;
    az = (az >= 0.f) ? az : LEAKY * az;
    aw = (aw >= 0.f) ? aw : LEAKY * aw;

    float act[4] = {ax, ay, az, aw};
    float o0 = 0.f, o1 = 0.f, o2 = 0.f, o3 = 0.f;
#pragma unroll
    for (int j = 0; j < 4; j++) {
        float4 wr = W2s[lane * 4 + j];
        o0 += act[j] * wr.x; o1 += act[j] * wr.y;
        o2 += act[j] * wr.z; o3 += act[j] * wr.w;
    }
#pragma unroll
    for (int off = 16; off; off >>= 1) {
        o0 += __shfl_down_sync(0xffffffffu, o0, off);
        o1 += __shfl_down_sync(0xffffffffu, o1, off);
        o2 += __shfl_down_sync(0xffffffffu, o2, off);
        o3 += __shfl_down_sync(0xffffffffu, o3, off);
    }
    if (lane == 0) g_hh[node] = make_float4(o0, o1, o2, o3);
}

// stream all edges (+ self loops), accumulate directly into per-graph buckets
__global__ void __launch_bounds__(256) k_pool(const int* __restrict__ src,
                                              const int* __restrict__ dst,
                                              const int* __restrict__ batch,
                                              int n, int E) {
    __shared__ float sb[NG * DO];
    if (threadIdx.x < NG * DO) sb[threadIdx.x] = 0.f;
    __syncthreads();
    int total = E + n;
    for (int i = blockIdx.x * blockDim.x + threadIdx.x; i < total;
         i += gridDim.x * blockDim.x) {
        int s, g; float w;
        if (i < E) {
            s = src[i];
            int d = dst[i];
            w = g_dis[s] * g_dis[d];
            g = batch[d];
        } else {
            int m = i - E;
            s = m;
            float dm = g_dis[m];
            w = dm * dm;
            g = batch[m];
        }
        float4 v = g_hh[s];
        atomicAdd(&sb[g * 4 + 0], v.x * w);
        atomicAdd(&sb[g * 4 + 1], v.y * w);
        atomicAdd(&sb[g * 4 + 2], v.z * w);
        atomicAdd(&sb[g * 4 + 3], v.w * w);
    }
    __syncthreads();
    if (threadIdx.x < NG * DO) atomicAdd(&g_pool[threadIdx.x], sb[threadIdx.x]);
}

// per-graph mean (+b2) and softmax; counts via binary search in sorted batch
__global__ void k_final(const int* __restrict__ batch, const float* __restrict__ b2,
                        float* __restrict__ out, int n) {
    int g = threadIdx.x;
    if (g >= NG) return;
    int lo = 0, hi = n;
    while (lo < hi) { int m = (lo + hi) >> 1; if (batch[m] < g) lo = m + 1; else hi = m; }
    int a = lo;
    lo = 0; hi = n;
    while (lo < hi) { int m = (lo + hi) >> 1; if (batch[m] < g + 1) lo = m + 1; else hi = m; }
    int c = lo - a;
    float v[4];
    if (c > 0) {
        float inv = 1.f / (float)c;
#pragma unroll
        for (int o = 0; o < 4; o++) v[o] = g_pool[g * 4 + o] * inv + b2[o];
    } else {
#pragma unroll
        for (int o = 0; o < 4; o++) v[o] = 0.f;
    }
    float mx = fmaxf(fmaxf(v[0], v[1]), fmaxf(v[2], v[3]));
    float e[4], s = 0.f;
#pragma unroll
    for (int o = 0; o < 4; o++) { e[o] = __expf(v[o] - mx); s += e[o]; }
    float inv = 1.f / s;
#pragma unroll
    for (int o = 0; o < 4; o++) out[g * 4 + o] = e[o] * inv;
}

// ---------------- launch ----------------
extern "C" void kernel_launch(void* const* d_in, const int* in_sizes, int n_in,
                              void* d_out, int out_size) {
    const float* x     = (const float*)d_in[0];
    const int*   ei    = (const int*)d_in[1];
    const int*   batch = (const int*)d_in[2];
    const float* W1    = (const float*)d_in[3];
    const float* b1    = (const float*)d_in[4];
    const float* W2    = (const float*)d_in[5];
    const float* b2    = (const float*)d_in[6];

    int n = in_sizes[0] / DD;
    int E = in_sizes[1] / 2;
    const int* src = ei;
    const int* dst = ei + E;
    int nb = (n + SCAN_B - 1) / SCAN_B;

    k_init<<<(n + 255) / 256, 256>>>(n);
    k_hist<<<(E + 255) / 256, 256>>>(dst, E);
    k_scan1<<<nb, SCAN_B>>>(n);
    k_scan2<<<1, 128>>>(nb, n);
    k_scan3<<<nb, SCAN_B>>>(n);
    k_scatter<<<(E + 255) / 256, 256>>>(src, dst, E);
    k_gemm<<<(n + 127) / 128, 256>>>(x, W1, n);
    k_prop<<<(n + 7) / 8, 256>>>(b1, W2, n);
    k_pool<<<1184, 256>>>(src, dst, batch, n, E);
    k_final<<<1, 64>>>(batch, b2, (float*)d_out, n);
}